// round 1
// baseline (speedup 1.0000x reference)
#include <cuda_runtime.h>
#include <cuda_bf16.h>
#include <cstdint>

// Problem constants
#define Bb   16
#define Ss   1024
#define DIN  1024
#define Hh   16
#define Ee   128
#define HE   (Hh * Ee)          // 2048
#define NQKV (Hh * 3 * Ee)      // 6144
#define MTOK (Bb * Ss)          // 16384

// GEMM tile config
#define BM 128
#define BN 128
#define BK 16
#define BMP 132                 // padded smem row stride (floats)
#define NTHREADS 256

// ---------------- scratch (device globals; no cudaMalloc allowed) ----------------
__device__ float g_q[(size_t)Bb * Hh * Ss * Ee];       // 33.5M
__device__ float g_k[(size_t)Bb * Hh * Ss * Ee];
__device__ float g_v[(size_t)Bb * Hh * Ss * Ee];
__device__ float g_scores[(size_t)Bb * Hh * Ss * Ss];  // 268M (1 GB)
__device__ float g_o[(size_t)Bb * Ss * HE];            // [B,S,H*E]

// ---------------- shared helpers ----------------

// Transpose-load: src row-major [rows, ld]; load tile rows [m0, m0+128), cols [k0, k0+16)
// into Ts[k][m] (padded stride BMP). Reads float4 along the contiguous k direction.
__device__ __forceinline__ void load_transpose(float Ts[BK][BMP],
                                               const float* __restrict__ src,
                                               size_t ld, int m0, int k0) {
#pragma unroll
    for (int r = 0; r < 2; ++r) {
        int idx = r * NTHREADS + threadIdx.x;   // 0..511
        int m = idx >> 2;                       // 0..127
        int kq = idx & 3;                       // 0..3
        float4 v = *(const float4*)&src[(size_t)(m0 + m) * ld + k0 + kq * 4];
        Ts[kq * 4 + 0][m] = v.x;
        Ts[kq * 4 + 1][m] = v.y;
        Ts[kq * 4 + 2][m] = v.z;
        Ts[kq * 4 + 3][m] = v.w;
    }
}

// Direct-load: src row-major [K, ld]; load tile rows [k0,k0+16) cols [n0,n0+128)
// into Ts[k][n] (padded stride BMP). float4 along contiguous n.
__device__ __forceinline__ void load_direct(float Ts[BK][BMP],
                                            const float* __restrict__ src,
                                            size_t ld, int k0, int n0) {
#pragma unroll
    for (int r = 0; r < 2; ++r) {
        int idx = r * NTHREADS + threadIdx.x;   // 0..511
        int k = idx >> 5;                       // 0..15
        int nq = idx & 31;                      // 0..31
        *(float4*)&Ts[k][nq * 4] =
            *(const float4*)&src[(size_t)(k0 + k) * ld + n0 + nq * 4];
    }
}

// 8x8 microkernel accumulation over one BK slab
__device__ __forceinline__ void mm_accum(const float As[BK][BMP],
                                         const float Bs[BK][BMP],
                                         float acc[8][8], int ty, int tx) {
#pragma unroll
    for (int kk = 0; kk < BK; ++kk) {
        float a[8], b[8];
        float4 a0 = *(const float4*)&As[kk][ty * 8];
        float4 a1 = *(const float4*)&As[kk][ty * 8 + 4];
        a[0]=a0.x; a[1]=a0.y; a[2]=a0.z; a[3]=a0.w;
        a[4]=a1.x; a[5]=a1.y; a[6]=a1.z; a[7]=a1.w;
        float4 b0 = *(const float4*)&Bs[kk][tx * 8];
        float4 b1 = *(const float4*)&Bs[kk][tx * 8 + 4];
        b[0]=b0.x; b[1]=b0.y; b[2]=b0.z; b[3]=b0.w;
        b[4]=b1.x; b[5]=b1.y; b[6]=b1.z; b[7]=b1.w;
#pragma unroll
        for (int i = 0; i < 8; ++i)
#pragma unroll
            for (int j = 0; j < 8; ++j)
                acc[i][j] += a[i] * b[j];
    }
}

// ---------------- kernel 1: QKV projection ----------------
// C[m, n] = sum_d x[m, d] * W[h, c, d, e]     n = (h*3 + c)*128 + e
__global__ __launch_bounds__(NTHREADS) void qkv_gemm(const float* __restrict__ x,
                                                     const float* __restrict__ W) {
    __shared__ float As[BK][BMP];
    __shared__ float Bs[BK][BMP];
    float acc[8][8] = {};
    int tx = threadIdx.x & 15, ty = threadIdx.x >> 4;

    int n0 = blockIdx.x * BN;         // 0..6143 in steps of 128
    int m0 = blockIdx.y * BM;
    int h  = n0 / 384;
    int c  = (n0 % 384) / 128;
    const float* wbase = W + (size_t)(h * 3 + c) * DIN * Ee;   // [DIN, Ee] slab

    for (int k0 = 0; k0 < DIN; k0 += BK) {
        load_transpose(As, x, DIN, m0, k0);
        load_direct(Bs, wbase, Ee, k0, 0);
        __syncthreads();
        mm_accum(As, Bs, acc, ty, tx);
        __syncthreads();
    }

    float* dst = (c == 0) ? g_q : (c == 1) ? g_k : g_v;
#pragma unroll
    for (int i = 0; i < 8; ++i) {
        int m = m0 + ty * 8 + i;
        int b = m >> 10, s = m & 1023;
        size_t base = ((size_t)(b * Hh + h) * Ss + s) * Ee + tx * 8;
        float4 c0 = make_float4(acc[i][0], acc[i][1], acc[i][2], acc[i][3]);
        float4 c1 = make_float4(acc[i][4], acc[i][5], acc[i][6], acc[i][7]);
        *(float4*)&dst[base]     = c0;
        *(float4*)&dst[base + 4] = c1;
    }
}

// ---------------- kernel 2: scores = Q K^T / 64 ----------------
__global__ __launch_bounds__(NTHREADS) void scores_gemm() {
    __shared__ float As[BK][BMP];
    __shared__ float Bs[BK][BMP];
    float acc[8][8] = {};
    int tx = threadIdx.x & 15, ty = threadIdx.x >> 4;

    int bh = blockIdx.z;
    int m0 = blockIdx.y * BM;   // query tile
    int n0 = blockIdx.x * BN;   // key tile
    const float* qp = g_q + (size_t)bh * Ss * Ee;
    const float* kp = g_k + (size_t)bh * Ss * Ee;

    for (int k0 = 0; k0 < Ee; k0 += BK) {
        load_transpose(As, qp, Ee, m0, k0);     // As[e][s]
        load_transpose(Bs, kp, Ee, n0, k0);     // Bs[e][t]
        __syncthreads();
        mm_accum(As, Bs, acc, ty, tx);
        __syncthreads();
    }

    const float scale = 1.0f / 64.0f;           // 1/(E*0.5)
    float* cp = g_scores + (size_t)bh * Ss * Ss;
#pragma unroll
    for (int i = 0; i < 8; ++i) {
        size_t base = (size_t)(m0 + ty * 8 + i) * Ss + n0 + tx * 8;
        float4 c0 = make_float4(acc[i][0]*scale, acc[i][1]*scale, acc[i][2]*scale, acc[i][3]*scale);
        float4 c1 = make_float4(acc[i][4]*scale, acc[i][5]*scale, acc[i][6]*scale, acc[i][7]*scale);
        *(float4*)&cp[base]     = c0;
        *(float4*)&cp[base + 4] = c1;
    }
}

// ---------------- kernel 3: row softmax over 1024 ----------------
__global__ __launch_bounds__(NTHREADS) void softmax_k() {
    size_t row = blockIdx.x;
    float* p = g_scores + row * Ss;
    int tid = threadIdx.x;
    float4 v = *(float4*)&p[tid * 4];

    __shared__ float red[NTHREADS];
    float m = fmaxf(fmaxf(v.x, v.y), fmaxf(v.z, v.w));
    red[tid] = m;
    __syncthreads();
#pragma unroll
    for (int s = NTHREADS / 2; s > 0; s >>= 1) {
        if (tid < s) red[tid] = fmaxf(red[tid], red[tid + s]);
        __syncthreads();
    }
    float rm = red[0];
    __syncthreads();

    v.x = __expf(v.x - rm); v.y = __expf(v.y - rm);
    v.z = __expf(v.z - rm); v.w = __expf(v.w - rm);
    red[tid] = v.x + v.y + v.z + v.w;
    __syncthreads();
#pragma unroll
    for (int s = NTHREADS / 2; s > 0; s >>= 1) {
        if (tid < s) red[tid] += red[tid + s];
        __syncthreads();
    }
    float inv = 1.0f / red[0];
    v.x *= inv; v.y *= inv; v.z *= inv; v.w *= inv;
    *(float4*)&p[tid * 4] = v;
}

// ---------------- kernel 4: O = P V,  store as [B,S,H*E] ----------------
__global__ __launch_bounds__(NTHREADS) void av_gemm() {
    __shared__ float As[BK][BMP];
    __shared__ float Bs[BK][BMP];
    float acc[8][8] = {};
    int tx = threadIdx.x & 15, ty = threadIdx.x >> 4;

    int bh = blockIdx.z;
    int b = bh >> 4, h = bh & 15;
    int m0 = blockIdx.y * BM;   // query tile; n0 = 0 (N = 128)
    const float* pp = g_scores + (size_t)bh * Ss * Ss;
    const float* vp = g_v + (size_t)bh * Ss * Ee;

    for (int k0 = 0; k0 < Ss; k0 += BK) {
        load_transpose(As, pp, Ss, m0, k0);   // As[t][s]
        load_direct(Bs, vp, Ee, k0, 0);       // Bs[t][e]
        __syncthreads();
        mm_accum(As, Bs, acc, ty, tx);
        __syncthreads();
    }

#pragma unroll
    for (int i = 0; i < 8; ++i) {
        int s = m0 + ty * 8 + i;
        size_t base = ((size_t)(b * Ss + s)) * HE + h * Ee + tx * 8;
        float4 c0 = make_float4(acc[i][0], acc[i][1], acc[i][2], acc[i][3]);
        float4 c1 = make_float4(acc[i][4], acc[i][5], acc[i][6], acc[i][7]);
        *(float4*)&g_o[base]     = c0;
        *(float4*)&g_o[base + 4] = c1;
    }
}

// ---------------- kernel 5: out = O @ Wo ----------------
__global__ __launch_bounds__(NTHREADS) void proj_gemm(const float* __restrict__ Wo,
                                                      float* __restrict__ out) {
    __shared__ float As[BK][BMP];
    __shared__ float Bs[BK][BMP];
    float acc[8][8] = {};
    int tx = threadIdx.x & 15, ty = threadIdx.x >> 4;

    int m0 = blockIdx.y * BM;   // N = 128 → single n tile

    for (int k0 = 0; k0 < HE; k0 += BK) {
        load_transpose(As, g_o, HE, m0, k0);
        load_direct(Bs, Wo, Ee, k0, 0);
        __syncthreads();
        mm_accum(As, Bs, acc, ty, tx);
        __syncthreads();
    }

#pragma unroll
    for (int i = 0; i < 8; ++i) {
        size_t base = (size_t)(m0 + ty * 8 + i) * Ee + tx * 8;
        float4 c0 = make_float4(acc[i][0], acc[i][1], acc[i][2], acc[i][3]);
        float4 c1 = make_float4(acc[i][4], acc[i][5], acc[i][6], acc[i][7]);
        *(float4*)&out[base]     = c0;
        *(float4*)&out[base + 4] = c1;
    }
}

// ---------------- launch ----------------
extern "C" void kernel_launch(void* const* d_in, const int* in_sizes, int n_in,
                              void* d_out, int out_size) {
    const float* x  = (const float*)d_in[0];   // [16,1024,1024]
    const float* W  = (const float*)d_in[1];   // [16,3,1024,128]
    const float* Wo = (const float*)d_in[2];   // [2048,128]
    float* out = (float*)d_out;                // [16,1024,128]

    qkv_gemm<<<dim3(NQKV / BN, MTOK / BM), NTHREADS>>>(x, W);            // 48 x 128
    scores_gemm<<<dim3(Ss / BN, Ss / BM, Bb * Hh), NTHREADS>>>();        // 8 x 8 x 256
    softmax_k<<<Bb * Hh * Ss, NTHREADS>>>();                             // 262144 rows
    av_gemm<<<dim3(1, Ss / BM, Bb * Hh), NTHREADS>>>();                  // 1 x 8 x 256
    proj_gemm<<<dim3(1, MTOK / BM), NTHREADS>>>(Wo, out);                // 1 x 128
}

// round 8
// speedup vs baseline: 1.0644x; 1.0644x over previous
#include <cuda_runtime.h>
#include <cuda_bf16.h>
#include <cstdint>

// Problem constants
#define Bb   16
#define Ss   1024
#define DIN  1024
#define Hh   16
#define Ee   128
#define HE   (Hh * Ee)          // 2048
#define NQKV (Hh * 3 * Ee)      // 6144
#define MTOK (Bb * Ss)          // 16384

// GEMM tile config
#define BM 128
#define BN 128
#define BK 16
#define BMP 132                 // padded smem row stride (floats)
#define NTHREADS 256

// ---------------- scratch (device globals; no cudaMalloc) ----------------
__device__ float g_q[(size_t)Bb * Hh * Ss * Ee];
__device__ float g_k[(size_t)Bb * Hh * Ss * Ee];
__device__ float g_v[(size_t)Bb * Hh * Ss * Ee];
__device__ float g_scores[(size_t)Bb * Hh * Ss * Ss];
__device__ float g_o[(size_t)Bb * Ss * HE];            // [B,S,H*E]

// ---------------- gmem fetch / smem store halves (R1 index maps, split) ----------------

// Transpose path: rows [m0,m0+128), cols [k0,k0+16) of src[.,ld] -> Ts[k][m]
__device__ __forceinline__ void ldg_trans(const float* __restrict__ src, size_t ld,
                                          int m0, int k0, float4 v[2]) {
    const int tid = threadIdx.x;
#pragma unroll
    for (int r = 0; r < 2; ++r) {
        int idx = r * NTHREADS + tid;           // 0..511
        int m = idx >> 2, kq = idx & 3;
        v[r] = *(const float4*)&src[(size_t)(m0 + m) * ld + k0 + kq * 4];
    }
}
__device__ __forceinline__ void sts_trans(float Ts[BK][BMP], const float4 v[2]) {
    const int tid = threadIdx.x;
#pragma unroll
    for (int r = 0; r < 2; ++r) {
        int idx = r * NTHREADS + tid;
        int m = idx >> 2, kq = idx & 3;
        Ts[kq * 4 + 0][m] = v[r].x;
        Ts[kq * 4 + 1][m] = v[r].y;
        Ts[kq * 4 + 2][m] = v[r].z;
        Ts[kq * 4 + 3][m] = v[r].w;
    }
}

// Direct path: rows [k0,k0+16), cols [n0,n0+128) of src[.,ld] -> Ts[k][n]
__device__ __forceinline__ void ldg_dir(const float* __restrict__ src, size_t ld,
                                        int k0, int n0, float4 v[2]) {
    const int tid = threadIdx.x;
#pragma unroll
    for (int r = 0; r < 2; ++r) {
        int idx = r * NTHREADS + tid;
        int k = idx >> 5, nq = idx & 31;
        v[r] = *(const float4*)&src[(size_t)(k0 + k) * ld + n0 + nq * 4];
    }
}
__device__ __forceinline__ void sts_dir(float Ts[BK][BMP], const float4 v[2]) {
    const int tid = threadIdx.x;
#pragma unroll
    for (int r = 0; r < 2; ++r) {
        int idx = r * NTHREADS + tid;
        int k = idx >> 5, nq = idx & 31;
        *(float4*)&Ts[k][nq * 4] = v[r];
    }
}

// ---------------- 8x8 microkernel over one BK slab (verbatim R1) ----------------
__device__ __forceinline__ void mm_accum(const float (*As)[BMP], const float (*Bs)[BMP],
                                         float acc[8][8], int ty, int tx) {
#pragma unroll
    for (int kk = 0; kk < BK; ++kk) {
        float a[8], b[8];
        float4 a0 = *(const float4*)&As[kk][ty * 8];
        float4 a1 = *(const float4*)&As[kk][ty * 8 + 4];
        a[0]=a0.x; a[1]=a0.y; a[2]=a0.z; a[3]=a0.w;
        a[4]=a1.x; a[5]=a1.y; a[6]=a1.z; a[7]=a1.w;
        float4 b0 = *(const float4*)&Bs[kk][tx * 8];
        float4 b1 = *(const float4*)&Bs[kk][tx * 8 + 4];
        b[0]=b0.x; b[1]=b0.y; b[2]=b0.z; b[3]=b0.w;
        b[4]=b1.x; b[5]=b1.y; b[6]=b1.z; b[7]=b1.w;
#pragma unroll
        for (int i = 0; i < 8; ++i)
#pragma unroll
            for (int j = 0; j < 8; ++j)
                acc[i][j] += a[i] * b[j];
    }
}

// ---------------- double-buffered mainloop: 1 sync per k-slab, LDG overlapped ----------------
template<bool BT>
__device__ __forceinline__ void mainloop(float (*As)[BK][BMP], float (*Bs)[BK][BMP],
    float acc[8][8],
    const float* __restrict__ A, size_t lda, int m0,
    const float* __restrict__ B, size_t ldb, int n0,
    int KT, int ty, int tx)
{
    float4 va[2], vb[2];
    ldg_trans(A, lda, m0, 0, va);
    if (BT) ldg_trans(B, ldb, n0, 0, vb); else ldg_dir(B, ldb, 0, n0, vb);
    sts_trans(As[0], va);
    if (BT) sts_trans(Bs[0], vb); else sts_dir(Bs[0], vb);
    __syncthreads();

    for (int kt = 0; kt < KT; ++kt) {
        const bool pf = (kt + 1 < KT);
        if (pf) {
            const int k1 = (kt + 1) * BK;
            ldg_trans(A, lda, m0, k1, va);
            if (BT) ldg_trans(B, ldb, n0, k1, vb); else ldg_dir(B, ldb, k1, n0, vb);
        }
        mm_accum(As[kt & 1], Bs[kt & 1], acc, ty, tx);
        if (pf) {
            sts_trans(As[(kt + 1) & 1], va);
            if (BT) sts_trans(Bs[(kt + 1) & 1], vb); else sts_dir(Bs[(kt + 1) & 1], vb);
            __syncthreads();
        }
    }
}

// ---------------- kernel 1: QKV projection ----------------
__global__ __launch_bounds__(NTHREADS, 2) void qkv_gemm(const float* __restrict__ x,
                                                        const float* __restrict__ W) {
    __shared__ float As[2][BK][BMP];
    __shared__ float Bs[2][BK][BMP];
    float acc[8][8] = {};
    int tx = threadIdx.x & 15, ty = threadIdx.x >> 4;

    int n0 = blockIdx.x * BN;
    int m0 = blockIdx.y * BM;
    int h  = n0 / 384;
    int c  = (n0 % 384) / 128;
    const float* wbase = W + (size_t)(h * 3 + c) * DIN * Ee;   // [DIN, Ee]

    mainloop<false>(As, Bs, acc, x, DIN, m0, wbase, Ee, 0, DIN / BK, ty, tx);

    float* dst = (c == 0) ? g_q : (c == 1) ? g_k : g_v;
#pragma unroll
    for (int i = 0; i < 8; ++i) {
        int m = m0 + ty * 8 + i;
        int b = m >> 10, s = m & 1023;
        size_t base = ((size_t)(b * Hh + h) * Ss + s) * Ee + tx * 8;
        *(float4*)&dst[base]     = make_float4(acc[i][0], acc[i][1], acc[i][2], acc[i][3]);
        *(float4*)&dst[base + 4] = make_float4(acc[i][4], acc[i][5], acc[i][6], acc[i][7]);
    }
}

// ---------------- kernel 2: scores = Q K^T / 64 ----------------
__global__ __launch_bounds__(NTHREADS, 2) void scores_gemm() {
    __shared__ float As[2][BK][BMP];
    __shared__ float Bs[2][BK][BMP];
    float acc[8][8] = {};
    int tx = threadIdx.x & 15, ty = threadIdx.x >> 4;

    int bh = blockIdx.z;
    int m0 = blockIdx.y * BM;
    int n0 = blockIdx.x * BN;
    const float* qp = g_q + (size_t)bh * Ss * Ee;
    const float* kp = g_k + (size_t)bh * Ss * Ee;

    mainloop<true>(As, Bs, acc, qp, Ee, m0, kp, Ee, n0, Ee / BK, ty, tx);

    const float scale = 1.0f / 64.0f;           // 1/(E*0.5)
    float* cp = g_scores + (size_t)bh * Ss * Ss;
#pragma unroll
    for (int i = 0; i < 8; ++i) {
        size_t base = (size_t)(m0 + ty * 8 + i) * Ss + n0 + tx * 8;
        *(float4*)&cp[base] =
            make_float4(acc[i][0]*scale, acc[i][1]*scale, acc[i][2]*scale, acc[i][3]*scale);
        *(float4*)&cp[base + 4] =
            make_float4(acc[i][4]*scale, acc[i][5]*scale, acc[i][6]*scale, acc[i][7]*scale);
    }
}

// ---------------- kernel 3: row softmax over 1024 (in place; rebuilt each call) ----------------
__global__ __launch_bounds__(NTHREADS) void softmax_k() {
    size_t row = blockIdx.x;
    float* p = g_scores + row * Ss;
    int tid = threadIdx.x;
    float4 v = *(float4*)&p[tid * 4];

    __shared__ float red[NTHREADS];
    float m = fmaxf(fmaxf(v.x, v.y), fmaxf(v.z, v.w));
    red[tid] = m;
    __syncthreads();
#pragma unroll
    for (int s = NTHREADS / 2; s > 0; s >>= 1) {
        if (tid < s) red[tid] = fmaxf(red[tid], red[tid + s]);
        __syncthreads();
    }
    float rm = red[0];
    __syncthreads();

    v.x = __expf(v.x - rm); v.y = __expf(v.y - rm);
    v.z = __expf(v.z - rm); v.w = __expf(v.w - rm);
    red[tid] = v.x + v.y + v.z + v.w;
    __syncthreads();
#pragma unroll
    for (int s = NTHREADS / 2; s > 0; s >>= 1) {
        if (tid < s) red[tid] += red[tid + s];
        __syncthreads();
    }
    float inv = 1.0f / red[0];
    v.x *= inv; v.y *= inv; v.z *= inv; v.w *= inv;
    *(float4*)&p[tid * 4] = v;
}

// ---------------- kernel 4: O = P V, store as [B,S,H*E] ----------------
__global__ __launch_bounds__(NTHREADS, 2) void av_gemm() {
    __shared__ float As[2][BK][BMP];
    __shared__ float Bs[2][BK][BMP];
    float acc[8][8] = {};
    int tx = threadIdx.x & 15, ty = threadIdx.x >> 4;

    int bh = blockIdx.z;
    int b = bh >> 4, h = bh & 15;
    int m0 = blockIdx.y * BM;
    const float* pp = g_scores + (size_t)bh * Ss * Ss;
    const float* vp = g_v + (size_t)bh * Ss * Ee;

    mainloop<false>(As, Bs, acc, pp, Ss, m0, vp, Ee, 0, Ss / BK, ty, tx);

#pragma unroll
    for (int i = 0; i < 8; ++i) {
        int s = m0 + ty * 8 + i;
        size_t base = ((size_t)(b * Ss + s)) * HE + h * Ee + tx * 8;
        *(float4*)&g_o[base]     = make_float4(acc[i][0], acc[i][1], acc[i][2], acc[i][3]);
        *(float4*)&g_o[base + 4] = make_float4(acc[i][4], acc[i][5], acc[i][6], acc[i][7]);
    }
}

// ---------------- kernel 5: out = O @ Wo ----------------
__global__ __launch_bounds__(NTHREADS, 2) void proj_gemm(const float* __restrict__ Wo,
                                                         float* __restrict__ out) {
    __shared__ float As[2][BK][BMP];
    __shared__ float Bs[2][BK][BMP];
    float acc[8][8] = {};
    int tx = threadIdx.x & 15, ty = threadIdx.x >> 4;

    int m0 = blockIdx.y * BM;   // N = 128 -> single n tile

    mainloop<false>(As, Bs, acc, g_o, HE, m0, Wo, Ee, 0, HE / BK, ty, tx);

#pragma unroll
    for (int i = 0; i < 8; ++i) {
        size_t base = (size_t)(m0 + ty * 8 + i) * Ee + tx * 8;
        *(float4*)&out[base]     = make_float4(acc[i][0], acc[i][1], acc[i][2], acc[i][3]);
        *(float4*)&out[base + 4] = make_float4(acc[i][4], acc[i][5], acc[i][6], acc[i][7]);
    }
}

// ---------------- launch ----------------
extern "C" void kernel_launch(void* const* d_in, const int* in_sizes, int n_in,
                              void* d_out, int out_size) {
    const float* x  = (const float*)d_in[0];   // [16,1024,1024]
    const float* W  = (const float*)d_in[1];   // [16,3,1024,128]
    const float* Wo = (const float*)d_in[2];   // [2048,128]
    float* out = (float*)d_out;                // [16,1024,128]

    qkv_gemm<<<dim3(NQKV / BN, MTOK / BM), NTHREADS>>>(x, W);            // 48 x 128
    scores_gemm<<<dim3(Ss / BN, Ss / BM, Bb * Hh), NTHREADS>>>();        // 8 x 8 x 256
    softmax_k<<<Bb * Hh * Ss, NTHREADS>>>();                             // 262144 rows
    av_gemm<<<dim3(1, Ss / BM, Bb * Hh), NTHREADS>>>();                  // 1 x 8 x 256
    proj_gemm<<<dim3(1, MTOK / BM), NTHREADS>>>(Wo, out);                // 1 x 128
}